// round 14
// baseline (speedup 1.0000x reference)
#include <cuda_runtime.h>
#include <cuda_bf16.h>
#include <cstdint>

// Problem constants (fixed by the reference)
#define PB 16
#define PC 128
#define PK 128
#define PD 256
#define BCD (PB*PC*PD)   // 524288
#define BKD (PB*PK*PD)   // 524288
#define CD  (PC*PD)      // 32768
#define KD  (PK*PD)      // 32768
#define NROWS (PB*PC*PK) // 262144 rows of out2, 1KB each
#define RZ1 212992       // kernel1 zerofill rows [0, RZ1)    : b in [0,13)
#define RZ2 229376       // kernel2 zerofill rows [RZ1, RZ2)  : b == 13
#define BFULL 14         // kernel3: b >= BFULL -> full write (zeros inline)

// Scratch (no allocations allowed -> __device__ globals)
__device__ float g_raw0[BCD];
__device__ float g_raw1[BKD];
__device__ float g_s0[BCD];
__device__ float g_s1[BKD];
__device__ float g_t1[BKD];     // kc * sigmoid(g1)

// ---------------------------------------------------------------------------
// tf32 helpers
// ---------------------------------------------------------------------------
__device__ __forceinline__ uint32_t f2tf32(float x) {
    uint32_t r;
    asm("cvt.rna.tf32.f32 %0, %1;" : "=r"(r) : "f"(x));
    return r;
}

__device__ __forceinline__ void mma_tf32(float* c, const uint32_t* a, const uint32_t* b) {
    asm volatile(
        "mma.sync.aligned.m16n8k8.row.col.f32.tf32.tf32.f32 "
        "{%0,%1,%2,%3}, {%4,%5,%6,%7}, {%8,%9}, {%0,%1,%2,%3};\n"
        : "+f"(c[0]), "+f"(c[1]), "+f"(c[2]), "+f"(c[3])
        : "r"(a[0]), "r"(a[1]), "r"(a[2]), "r"(a[3]), "r"(b[0]), "r"(b[1]));
}

// ---------------------------------------------------------------------------
// Uniform grid-stride zerofill over flattened (b,c,k) rows of out2.
// ---------------------------------------------------------------------------
__device__ __forceinline__ void zerofill_rows(
    float* __restrict__ out2, const int* __restrict__ cmask,
    const int* __restrict__ kmask, int row_begin, int row_end,
    int nblocks, int bid, int tid)
{
    const int lane = tid & 63;
    const int rsub = tid >> 6;
    const float4 z4 = make_float4(0.f, 0.f, 0.f, 0.f);
    for (int base = row_begin + bid * 4; base < row_end; base += nblocks * 4) {
        const int row = base + rsub;
        if (row < row_end) {
            const int b = row >> 14;
            const int c = (row >> 7) & 127;
            const int k = row & 127;
            if (!(cmask[b * PC + c] & kmask[b * PK + k])) {
                float4* p = (float4*)(out2 + (long)row * PD);
                __stcs(&p[lane], z4);
            }
        }
    }
}

// ---------------------------------------------------------------------------
// kernel1: blocks [0,256) = tensor-core 3xTF32 dual GEMM (R12 v1 body,
//          accuracy-proven, 24us solo); blocks [256,256+ZB1) = zerofill
//          rows [0, RZ1) (~160MB of zeros).
// ---------------------------------------------------------------------------
#define ZB1 768
__global__ void kernel1(
    const float* __restrict__ q, const float* __restrict__ kc,
    const float* __restrict__ W0, const float* __restrict__ W1,
    float* __restrict__ o0, float* __restrict__ o1,
    const int* __restrict__ cmask, const int* __restrict__ kmask,
    float* __restrict__ out2)
{
    const int tid = threadIdx.x;

    if (blockIdx.x >= 256) {
        zerofill_rows(out2, cmask, kmask, 0, RZ1, ZB1, blockIdx.x - 256, tid);
        return;
    }

    // ---------------- GEMM role (tf32 v1) ----------------
    const int rem = blockIdx.x & 127;
    const int z   = blockIdx.x >> 7;
    const int m0  = (rem >> 2) * 64;
    const int n0  = (rem & 3) * 64;

    const float* A  = z ? kc : q;
    const float* Bm = z ? W1 : W0;
    float*       C  = z ? o1 : o0;

    __shared__ __align__(16) float As[32][68];   // As[k][m]
    __shared__ __align__(16) float Bs[32][68];   // Bs[k][n]

    const int warp = tid >> 5;
    const int lane = tid & 31;
    const int gid  = lane >> 2;
    const int tg   = lane & 3;
    const int mw   = (warp & 3) * 16;
    const int nw   = (warp >> 2) * 32;

    const int lr  = tid >> 2;
    const int lcb = (tid & 3) * 8;
    const float* Ap = A  + (long)(m0 + lr) * 256 + lcb;
    const float* Bp = Bm + (long)(n0 + lr) * 256 + lcb;

    float c[4][4];
#pragma unroll
    for (int s = 0; s < 4; s++)
#pragma unroll
        for (int i = 0; i < 4; i++) c[s][i] = 0.f;

    float4 a0 = *(const float4*)Ap;
    float4 a1 = *(const float4*)(Ap + 4);
    float4 b0 = *(const float4*)Bp;
    float4 b1 = *(const float4*)(Bp + 4);

    for (int k0 = 0; k0 < 256; k0 += 32) {
        As[lcb+0][lr] = a0.x; As[lcb+1][lr] = a0.y; As[lcb+2][lr] = a0.z; As[lcb+3][lr] = a0.w;
        As[lcb+4][lr] = a1.x; As[lcb+5][lr] = a1.y; As[lcb+6][lr] = a1.z; As[lcb+7][lr] = a1.w;
        Bs[lcb+0][lr] = b0.x; Bs[lcb+1][lr] = b0.y; Bs[lcb+2][lr] = b0.z; Bs[lcb+3][lr] = b0.w;
        Bs[lcb+4][lr] = b1.x; Bs[lcb+5][lr] = b1.y; Bs[lcb+6][lr] = b1.z; Bs[lcb+7][lr] = b1.w;
        __syncthreads();

        if (k0 + 32 < 256) {
            a0 = *(const float4*)(Ap + k0 + 32);
            a1 = *(const float4*)(Ap + k0 + 36);
            b0 = *(const float4*)(Bp + k0 + 32);
            b1 = *(const float4*)(Bp + k0 + 36);
        }

#pragma unroll
        for (int ks = 0; ks < 4; ks++) {
            const int klo = ks * 8;
            float af[4];
            af[0] = As[klo + tg    ][mw + gid];
            af[1] = As[klo + tg    ][mw + gid + 8];
            af[2] = As[klo + tg + 4][mw + gid];
            af[3] = As[klo + tg + 4][mw + gid + 8];
            uint32_t ah[4], al[4];
#pragma unroll
            for (int i = 0; i < 4; i++) {
                ah[i] = f2tf32(af[i]);
                al[i] = f2tf32(af[i] - __uint_as_float(ah[i]));
            }
#pragma unroll
            for (int s = 0; s < 4; s++) {
                const int ns = nw + s * 8;
                float bf[2];
                bf[0] = Bs[klo + tg    ][ns + gid];
                bf[1] = Bs[klo + tg + 4][ns + gid];
                uint32_t bh[2], bl[2];
#pragma unroll
                for (int i = 0; i < 2; i++) {
                    bh[i] = f2tf32(bf[i]);
                    bl[i] = f2tf32(bf[i] - __uint_as_float(bh[i]));
                }
                mma_tf32(c[s], ah, bh);
                mma_tf32(c[s], ah, bl);
                mma_tf32(c[s], al, bh);
            }
        }
        __syncthreads();
    }

#pragma unroll
    for (int s = 0; s < 4; s++) {
        const int col = n0 + nw + s * 8 + 2 * tg;
        const long r0 = m0 + mw + gid;
        *(float2*)&C[r0 * 256 + col]       = make_float2(c[s][0], c[s][1]);
        *(float2*)&C[(r0 + 8) * 256 + col] = make_float2(c[s][2], c[s][3]);
    }
}

// ---------------------------------------------------------------------------
// kernel2: blocks [0,256) BN stats+apply+sigmoid+t1;
//          blocks [256, 256+ZB2) zerofill rows [RZ1, RZ2)  (~12MB)
// ---------------------------------------------------------------------------
#define ZB2 256
__global__ void __launch_bounds__(256, 4) kernel2(
    const float* __restrict__ gamma0, const float* __restrict__ beta0,
    const float* __restrict__ gamma1, const float* __restrict__ beta1,
    const float* __restrict__ kc,
    const int* __restrict__ cmask, const int* __restrict__ kmask,
    float* __restrict__ out2)
{
    const int tid = threadIdx.x;

    if (blockIdx.x >= 256) {
        zerofill_rows(out2, cmask, kmask, RZ1, RZ2, ZB2, blockIdx.x - 256, tid);
        return;
    }

    const int cb = blockIdx.x;
    const int c  = cb & 127;
    const int is1 = (cb >> 7);
    const float* src = is1 ? g_raw1 : g_raw0;
    const int t = tid;                    // t == d

    float s = 0.f, ss = 0.f;
    const float* p = src + c * PD + t;
#pragma unroll
    for (int b = 0; b < PB; b++) {
        float v = p[b * CD];
        s += v; ss += v * v;
    }

    __shared__ float sh[256], sh2[256];
    sh[t] = s; sh2[t] = ss;
    __syncthreads();
    for (int o = 128; o > 0; o >>= 1) {
        if (t < o) { sh[t] += sh[t + o]; sh2[t] += sh2[t + o]; }
        __syncthreads();
    }
    __shared__ float s_sc, s_sf;
    if (t == 0) {
        const float inv_n = 1.f / 4096.f;
        float mean = sh[0] * inv_n;
        float var  = sh2[0] * inv_n - mean * mean;
        float g  = is1 ? gamma1[c] : gamma0[c];
        float be = is1 ? beta1[c]  : beta0[c];
        float sc = g * rsqrtf(var + 1e-5f);
        s_sc = sc;
        s_sf = be - mean * sc;
    }
    __syncthreads();
    const float sc = s_sc, sf = s_sf;

    if (!is1) {
        float* dst = g_s0 + c * PD + t;
#pragma unroll
        for (int b = 0; b < PB; b++) {
            float v = p[b * CD];
            dst[b * CD] = 1.f / (1.f + __expf(-(v * sc + sf)));
        }
    } else {
        float* dsts = g_s1 + c * PD + t;
        float* dstt = g_t1 + c * PD + t;
        const float* kcp = kc + c * PD + t;
#pragma unroll
        for (int b = 0; b < PB; b++) {
            float v = p[b * CD];
            float sv = 1.f / (1.f + __expf(-(v * sc + sf)));
            dsts[b * CD] = sv;
            dstt[b * CD] = kcp[b * CD] * sv;
        }
    }
}

// ---------------------------------------------------------------------------
// kernel3: [0,64) out3 GEMM; [64,576) stream:
//   b >= BFULL: full write (zeros inline, R6-proven body)
//   b <  BFULL: nonzero-only writes (zeros already done by k1/k2)
// ---------------------------------------------------------------------------
__global__ void __launch_bounds__(256, 4) kernel3(
    const int* __restrict__ cmask, const int* __restrict__ kmask,
    const int* __restrict__ klen,
    float* __restrict__ out1, float* __restrict__ out2, float* __restrict__ out3)
{
    const int tid = threadIdx.x;

    if (blockIdx.x < 64) {
        // ---------------- out3 GEMM role ----------------
        const int idx  = blockIdx.x;
        const int bz   = idx >> 2;
        const int tile = idx & 3;
        const int m0 = (tile >> 1) * 64;
        const int n0 = (tile & 1) * 64;

        const float* Ab = g_s0 + (long)bz * CD;
        const float* Bb = g_s1 + (long)bz * KD;
        float*       Cb = out3 + (long)bz * PC * PK;

        __shared__ __align__(16) float As[16][68];
        __shared__ __align__(16) float Bs[16][68];

        const int tx = tid & 15;
        const int ty = tid >> 4;
        const int kk = tid & 15;
        const int r  = tid >> 4;

        float acc[4][4];
#pragma unroll
        for (int i = 0; i < 4; i++)
#pragma unroll
            for (int j = 0; j < 4; j++) acc[i][j] = 0.f;

        for (int k0 = 0; k0 < 256; k0 += 16) {
#pragma unroll
            for (int p = 0; p < 4; p++) {
                As[kk][r + p*16] = Ab[(long)(m0 + r + p*16) * 256 + k0 + kk];
                Bs[kk][r + p*16] = Bb[(long)(n0 + r + p*16) * 256 + k0 + kk];
            }
            __syncthreads();
#pragma unroll
            for (int kq = 0; kq < 16; kq++) {
                float4 av = *(const float4*)&As[kq][ty * 4];
                float4 bv = *(const float4*)&Bs[kq][tx * 4];
                acc[0][0] += av.x*bv.x; acc[0][1] += av.x*bv.y; acc[0][2] += av.x*bv.z; acc[0][3] += av.x*bv.w;
                acc[1][0] += av.y*bv.x; acc[1][1] += av.y*bv.y; acc[1][2] += av.y*bv.z; acc[1][3] += av.y*bv.w;
                acc[2][0] += av.z*bv.x; acc[2][1] += av.z*bv.y; acc[2][2] += av.z*bv.z; acc[2][3] += av.z*bv.w;
                acc[3][0] += av.w*bv.x; acc[3][1] += av.w*bv.y; acc[3][2] += av.w*bv.z; acc[3][3] += av.w*bv.w;
            }
            __syncthreads();
        }

#pragma unroll
        for (int i = 0; i < 4; i++) {
            const long row = m0 + ty*4 + i;
#pragma unroll
            for (int j = 0; j < 4; j++)
                Cb[row * PK + n0 + tx*4 + j] = acc[i][j] * (1.f / 256.f);
        }
        return;
    }

    // ---------------- stream role ----------------
    const int sb = blockIdx.x - 64;
    const int c0 = (sb & 31) * 4;
    const int b  = sb >> 5;
    const int dq = tid & 63;
    const int ks = tid >> 6;

    __shared__ int skm[PK];
    if (tid < PK) skm[tid] = kmask[b * PK + tid];

    float4 s0d[4];
    int cm[4];
#pragma unroll
    for (int j = 0; j < 4; j++) {
        s0d[j] = ((const float4*)(g_s0 + (long)(b * PC + c0 + j) * PD))[dq];
        cm[j]  = cmask[b * PC + c0 + j];
    }
    const int anyc = cm[0] | cm[1] | cm[2] | cm[3];
    const float invlen = 1.f / (float)klen[b];
    const float4* t1v = (const float4*)(g_t1 + (long)b * KD) + dq;
    float4* o2 = (float4*)(out2 + (long)(b * PC + c0) * KD) + dq;
    __syncthreads();

    float4 acc[4];
#pragma unroll
    for (int j = 0; j < 4; j++) acc[j] = make_float4(0.f, 0.f, 0.f, 0.f);

    if (b >= BFULL) {
        for (int k = ks; k < PK; k += 4) {
            const int m = skm[k] & anyc;
            float4 t = make_float4(0.f, 0.f, 0.f, 0.f);
            if (m) t = t1v[k * 64];
#pragma unroll
            for (int j = 0; j < 4; j++) {
                float4 v = make_float4(0.f, 0.f, 0.f, 0.f);
                if (m & cm[j]) {
                    v.x = t.x * s0d[j].x; v.y = t.y * s0d[j].y;
                    v.z = t.z * s0d[j].z; v.w = t.w * s0d[j].w;
                    acc[j].x += v.x; acc[j].y += v.y; acc[j].z += v.z; acc[j].w += v.w;
                }
                __stcs(&o2[(long)j * (KD / 4) + k * 64], v);
            }
        }
    } else {
        for (int k = ks; k < PK; k += 4) {
            const int m = skm[k] & anyc;
            if (m) {
                float4 t = t1v[k * 64];
#pragma unroll
                for (int j = 0; j < 4; j++) {
                    if (m & cm[j]) {
                        float4 v;
                        v.x = t.x * s0d[j].x; v.y = t.y * s0d[j].y;
                        v.z = t.z * s0d[j].z; v.w = t.w * s0d[j].w;
                        acc[j].x += v.x; acc[j].y += v.y; acc[j].z += v.z; acc[j].w += v.w;
                        __stcs(&o2[(long)j * (KD / 4) + k * 64], v);
                    }
                }
            }
        }
    }

    __shared__ float4 sh4[256];
#pragma unroll
    for (int j = 0; j < 4; j++) {
        __syncthreads();
        sh4[tid] = acc[j];
        __syncthreads();
        if (tid < 64) {
            float4 a = sh4[tid], b4 = sh4[tid + 64], c4 = sh4[tid + 128], d4 = sh4[tid + 192];
            float4 r;
            r.x = tanhf((a.x + b4.x + c4.x + d4.x) * invlen);
            r.y = tanhf((a.y + b4.y + c4.y + d4.y) * invlen);
            r.z = tanhf((a.z + b4.z + c4.z + d4.z) * invlen);
            r.w = tanhf((a.w + b4.w + c4.w + d4.w) * invlen);
            ((float4*)(out1 + (long)(b * PC + c0 + j) * PD))[tid] = r;
        }
    }
}

// ---------------------------------------------------------------------------
extern "C" void kernel_launch(void* const* d_in, const int* in_sizes, int n_in,
                              void* d_out, int out_size)
{
    const float* q      = (const float*)d_in[0];   // (B,C,D)
    const float* kc     = (const float*)d_in[1];   // (B,K,D)
    const float* W0     = (const float*)d_in[2];   // (D,D)
    const float* W1     = (const float*)d_in[3];   // (D,D)
    const float* bn0_g  = (const float*)d_in[4];
    const float* bn0_b  = (const float*)d_in[5];
    const float* bn1_g  = (const float*)d_in[6];
    const float* bn1_b  = (const float*)d_in[7];
    const int*   cmask  = (const int*)d_in[8];     // (B,C)
    const int*   kmask  = (const int*)d_in[9];     // (B,K)
    const int*   klen   = (const int*)d_in[10];    // (B,)

    float* out  = (float*)d_out;
    float* out1 = out;                                   // (B,C,D)
    float* out2 = out + (long)BCD;                       // (B,C,K,D)
    float* out3 = out + (long)BCD + (long)PB*PC*PK*PD;   // (B,C,K)

    float *raw0, *raw1;
    cudaGetSymbolAddress((void**)&raw0, g_raw0);
    cudaGetSymbolAddress((void**)&raw1, g_raw1);

    // 1) tf32 tensor-core dual GEMM + zerofill rows [0, RZ1)  (~160MB zeros)
    kernel1<<<256 + ZB1, 256>>>(q, kc, W0, W1, raw0, raw1, cmask, kmask, out2);

    // 2) BN stats+apply+sigmoid+t1 + zerofill rows [RZ1, RZ2) (~12MB zeros)
    kernel2<<<256 + ZB2, 256>>>(bn0_g, bn0_b, bn1_g, bn1_b, kc, cmask, kmask, out2);

    // 3) out3 GEMM + stream (full write b>=14, nonzero-only below) + out1
    kernel3<<<64 + 512, 256>>>(cmask, kmask, klen, out1, out2, out3);
}

// round 15
// speedup vs baseline: 1.1557x; 1.1557x over previous
#include <cuda_runtime.h>
#include <cuda_bf16.h>

// Problem constants (fixed by the reference)
#define PB 16
#define PC 128
#define PK 128
#define PD 256
#define BCD (PB*PC*PD)   // 524288
#define BKD (PB*PK*PD)   // 524288
#define CD  (PC*PD)      // 32768
#define KD  (PK*PD)      // 32768
#define NROWS (PB*PC*PK) // 262144 rows of out2, 1KB each

// Scratch (no allocations allowed -> __device__ globals)
__device__ float g_raw0[BCD];
__device__ float g_raw1[BKD];
__device__ float g_s0[BCD];
__device__ float g_s1[BKD];
__device__ float g_t1[BKD];     // kc * sigmoid(g1)

// ---------------------------------------------------------------------------
// kernel1: blocks [0,256) dual GEMM (prefetch, uncapped regs — R10 body);
//          blocks [256, 2304) zerofill ALL mask-zero rows (~200MB).
// k1 duration = max(zero stream ~43us, GEMM stretch ~33us) -> zero-bound.
// ---------------------------------------------------------------------------
#define ZB1 2048
__global__ void kernel1(
    const float* __restrict__ q, const float* __restrict__ kc,
    const float* __restrict__ W0, const float* __restrict__ W1,
    float* __restrict__ o0, float* __restrict__ o1,
    const int* __restrict__ cmask, const int* __restrict__ kmask,
    float* __restrict__ out2)
{
    const int tid = threadIdx.x;

    if (blockIdx.x >= 256) {
        // ---------------- zerofill role ----------------
        const int bid  = blockIdx.x - 256;
        const int lane = tid & 63;
        const int rsub = tid >> 6;
        const float4 z4 = make_float4(0.f, 0.f, 0.f, 0.f);
        for (int base = bid * 4; base < NROWS; base += ZB1 * 4) {
            const int row = base + rsub;
            const int b = row >> 14;
            const int c = (row >> 7) & 127;
            const int k = row & 127;
            if (!(cmask[b * PC + c] & kmask[b * PK + k])) {
                float4* p = (float4*)(out2 + (long)row * PD);
                __stcs(&p[lane], z4);
            }
        }
        return;
    }

    // ---------------- GEMM role (prefetch, 32-slab) ----------------
    const int rem = blockIdx.x & 127;
    const int z   = blockIdx.x >> 7;
    const int n0  = (rem & 3) * 64;
    const int m0  = (rem >> 2) * 64;

    const float* A  = z ? kc : q;
    const float* Bm = z ? W1 : W0;
    float*       C  = z ? o1 : o0;

    __shared__ __align__(16) float As[32][68];
    __shared__ __align__(16) float Bs[32][68];

    const int tx = tid & 15;
    const int ty = tid >> 4;
    const int lr  = tid >> 2;
    const int lcb = (tid & 3) * 8;

    const float* Ap = A  + (long)(m0 + lr) * 256 + lcb;
    const float* Bp = Bm + (long)(n0 + lr) * 256 + lcb;

    float acc[4][4];
#pragma unroll
    for (int i = 0; i < 4; i++)
#pragma unroll
        for (int j = 0; j < 4; j++) acc[i][j] = 0.f;

    float4 a0 = *(const float4*)Ap;
    float4 a1 = *(const float4*)(Ap + 4);
    float4 b0 = *(const float4*)Bp;
    float4 b1 = *(const float4*)(Bp + 4);

    for (int k0 = 0; k0 < 256; k0 += 32) {
        As[lcb+0][lr] = a0.x; As[lcb+1][lr] = a0.y; As[lcb+2][lr] = a0.z; As[lcb+3][lr] = a0.w;
        As[lcb+4][lr] = a1.x; As[lcb+5][lr] = a1.y; As[lcb+6][lr] = a1.z; As[lcb+7][lr] = a1.w;
        Bs[lcb+0][lr] = b0.x; Bs[lcb+1][lr] = b0.y; Bs[lcb+2][lr] = b0.z; Bs[lcb+3][lr] = b0.w;
        Bs[lcb+4][lr] = b1.x; Bs[lcb+5][lr] = b1.y; Bs[lcb+6][lr] = b1.z; Bs[lcb+7][lr] = b1.w;
        __syncthreads();

        if (k0 + 32 < 256) {
            a0 = *(const float4*)(Ap + k0 + 32);
            a1 = *(const float4*)(Ap + k0 + 36);
            b0 = *(const float4*)(Bp + k0 + 32);
            b1 = *(const float4*)(Bp + k0 + 36);
        }

#pragma unroll
        for (int kq = 0; kq < 32; kq++) {
            float4 av = *(const float4*)&As[kq][ty * 4];
            float4 bv = *(const float4*)&Bs[kq][tx * 4];
            acc[0][0] += av.x*bv.x; acc[0][1] += av.x*bv.y; acc[0][2] += av.x*bv.z; acc[0][3] += av.x*bv.w;
            acc[1][0] += av.y*bv.x; acc[1][1] += av.y*bv.y; acc[1][2] += av.y*bv.z; acc[1][3] += av.y*bv.w;
            acc[2][0] += av.z*bv.x; acc[2][1] += av.z*bv.y; acc[2][2] += av.z*bv.z; acc[2][3] += av.z*bv.w;
            acc[3][0] += av.w*bv.x; acc[3][1] += av.w*bv.y; acc[3][2] += av.w*bv.z; acc[3][3] += av.w*bv.w;
        }
        __syncthreads();
    }

#pragma unroll
    for (int i = 0; i < 4; i++) {
        float4 r = make_float4(acc[i][0], acc[i][1], acc[i][2], acc[i][3]);
        *(float4*)&C[(long)(m0 + ty*4 + i) * 256 + n0 + tx*4] = r;
    }
}

// ---------------------------------------------------------------------------
// bn_merged: 1 block per channel (256: [0..127]=bn0/s0, [128..255]=bn1/s1,t1)
// ---------------------------------------------------------------------------
__global__ void bn_merged(const float* __restrict__ gamma0, const float* __restrict__ beta0,
                          const float* __restrict__ gamma1, const float* __restrict__ beta1,
                          const float* __restrict__ kc)
{
    const int cb = blockIdx.x;
    const int c  = cb & 127;
    const int is1 = (cb >> 7);
    const float* src = is1 ? g_raw1 : g_raw0;
    const int t = threadIdx.x;            // t == d

    float s = 0.f, ss = 0.f;
    const float* p = src + c * PD + t;
#pragma unroll
    for (int b = 0; b < PB; b++) {
        float v = p[b * CD];
        s += v; ss += v * v;
    }

    __shared__ float sh[256], sh2[256];
    sh[t] = s; sh2[t] = ss;
    __syncthreads();
    for (int o = 128; o > 0; o >>= 1) {
        if (t < o) { sh[t] += sh[t + o]; sh2[t] += sh2[t + o]; }
        __syncthreads();
    }
    __shared__ float s_sc, s_sf;
    if (t == 0) {
        const float inv_n = 1.f / 4096.f;
        float mean = sh[0] * inv_n;
        float var  = sh2[0] * inv_n - mean * mean;
        float g  = is1 ? gamma1[c] : gamma0[c];
        float be = is1 ? beta1[c]  : beta0[c];
        float sc = g * rsqrtf(var + 1e-5f);
        s_sc = sc;
        s_sf = be - mean * sc;
    }
    __syncthreads();
    const float sc = s_sc, sf = s_sf;

    if (!is1) {
        float* dst = g_s0 + c * PD + t;
#pragma unroll
        for (int b = 0; b < PB; b++) {
            float v = p[b * CD];
            dst[b * CD] = 1.f / (1.f + __expf(-(v * sc + sf)));
        }
    } else {
        float* dsts = g_s1 + c * PD + t;
        float* dstt = g_t1 + c * PD + t;
        const float* kcp = kc + c * PD + t;
#pragma unroll
        for (int b = 0; b < PB; b++) {
            float v = p[b * CD];
            float sv = 1.f / (1.f + __expf(-(v * sc + sf)));
            dsts[b * CD] = sv;
            dstt[b * CD] = kcp[b * CD] * sv;
        }
    }
}

// ---------------------------------------------------------------------------
// kernel3: [0,64) out3 GEMM; [64, 64+SB3) persistent stream blocks covering
//          1024 (b, c-pair) units grid-stride (nonzero-only writes + out1).
// Finer work quantum + stealing flattens the mask-dependent straggler tail.
// ---------------------------------------------------------------------------
#define SB3 448
__global__ void __launch_bounds__(256, 4) kernel3(
    const int* __restrict__ cmask, const int* __restrict__ kmask,
    const int* __restrict__ klen,
    float* __restrict__ out1, float* __restrict__ out2, float* __restrict__ out3)
{
    const int tid = threadIdx.x;

    if (blockIdx.x < 64) {
        // ---------------- out3 GEMM role ----------------
        const int idx  = blockIdx.x;
        const int bz   = idx >> 2;
        const int tile = idx & 3;
        const int m0 = (tile >> 1) * 64;
        const int n0 = (tile & 1) * 64;

        const float* Ab = g_s0 + (long)bz * CD;
        const float* Bb = g_s1 + (long)bz * KD;
        float*       Cb = out3 + (long)bz * PC * PK;

        __shared__ __align__(16) float As[16][68];
        __shared__ __align__(16) float Bs[16][68];

        const int tx = tid & 15;
        const int ty = tid >> 4;
        const int kk = tid & 15;
        const int r  = tid >> 4;

        float acc[4][4];
#pragma unroll
        for (int i = 0; i < 4; i++)
#pragma unroll
            for (int j = 0; j < 4; j++) acc[i][j] = 0.f;

        for (int k0 = 0; k0 < 256; k0 += 16) {
#pragma unroll
            for (int p = 0; p < 4; p++) {
                As[kk][r + p*16] = Ab[(long)(m0 + r + p*16) * 256 + k0 + kk];
                Bs[kk][r + p*16] = Bb[(long)(n0 + r + p*16) * 256 + k0 + kk];
            }
            __syncthreads();
#pragma unroll
            for (int kq = 0; kq < 16; kq++) {
                float4 av = *(const float4*)&As[kq][ty * 4];
                float4 bv = *(const float4*)&Bs[kq][tx * 4];
                acc[0][0] += av.x*bv.x; acc[0][1] += av.x*bv.y; acc[0][2] += av.x*bv.z; acc[0][3] += av.x*bv.w;
                acc[1][0] += av.y*bv.x; acc[1][1] += av.y*bv.y; acc[1][2] += av.y*bv.z; acc[1][3] += av.y*bv.w;
                acc[2][0] += av.z*bv.x; acc[2][1] += av.z*bv.y; acc[2][2] += av.z*bv.z; acc[2][3] += av.z*bv.w;
                acc[3][0] += av.w*bv.x; acc[3][1] += av.w*bv.y; acc[3][2] += av.w*bv.z; acc[3][3] += av.w*bv.w;
            }
            __syncthreads();
        }

#pragma unroll
        for (int i = 0; i < 4; i++) {
            const long row = m0 + ty*4 + i;
#pragma unroll
            for (int j = 0; j < 4; j++)
                Cb[row * PK + n0 + tx*4 + j] = acc[i][j] * (1.f / 256.f);
        }
        return;
    }

    // ---------------- persistent stream role ----------------
    const int dq = tid & 63;
    const int ks = tid >> 6;

    __shared__ int skm[PK];
    __shared__ float4 sh4[256];

    for (int u = blockIdx.x - 64; u < 1024; u += SB3) {
        const int b  = u >> 6;          // 16 b x 64 c-pairs
        const int c0 = (u & 63) * 2;

        __syncthreads();                // protect skm from previous unit
        if (tid < PK) skm[tid] = kmask[b * PK + tid];

        float4 s0d[2];
        int cm[2];
#pragma unroll
        for (int j = 0; j < 2; j++) {
            s0d[j] = ((const float4*)(g_s0 + (long)(b * PC + c0 + j) * PD))[dq];
            cm[j]  = cmask[b * PC + c0 + j];
        }
        const int anyc = cm[0] | cm[1];
        const float invlen = 1.f / (float)klen[b];
        const float4* t1v = (const float4*)(g_t1 + (long)b * KD) + dq;
        float4* o2 = (float4*)(out2 + (long)(b * PC + c0) * KD) + dq;
        __syncthreads();

        float4 acc[2];
#pragma unroll
        for (int j = 0; j < 2; j++) acc[j] = make_float4(0.f, 0.f, 0.f, 0.f);

        if (anyc) {
            for (int k = ks; k < PK; k += 4) {
                const int m = skm[k];
                if (m) {
                    float4 t = t1v[k * 64];
#pragma unroll
                    for (int j = 0; j < 2; j++) {
                        if (cm[j]) {
                            float4 v;
                            v.x = t.x * s0d[j].x; v.y = t.y * s0d[j].y;
                            v.z = t.z * s0d[j].z; v.w = t.w * s0d[j].w;
                            acc[j].x += v.x; acc[j].y += v.y; acc[j].z += v.z; acc[j].w += v.w;
                            __stcs(&o2[(long)j * (KD / 4) + k * 64], v);
                        }
                    }
                }
            }
        }

        // out1 for the 2 c rows
#pragma unroll
        for (int j = 0; j < 2; j++) {
            __syncthreads();
            sh4[tid] = acc[j];
            __syncthreads();
            if (tid < 64) {
                float4 a = sh4[tid], b4 = sh4[tid + 64], c4 = sh4[tid + 128], d4 = sh4[tid + 192];
                float4 r;
                r.x = tanhf((a.x + b4.x + c4.x + d4.x) * invlen);
                r.y = tanhf((a.y + b4.y + c4.y + d4.y) * invlen);
                r.z = tanhf((a.z + b4.z + c4.z + d4.z) * invlen);
                r.w = tanhf((a.w + b4.w + c4.w + d4.w) * invlen);
                ((float4*)(out1 + (long)(b * PC + c0 + j) * PD))[tid] = r;
            }
        }
    }
}

// ---------------------------------------------------------------------------
extern "C" void kernel_launch(void* const* d_in, const int* in_sizes, int n_in,
                              void* d_out, int out_size)
{
    const float* q      = (const float*)d_in[0];   // (B,C,D)
    const float* kc     = (const float*)d_in[1];   // (B,K,D)
    const float* W0     = (const float*)d_in[2];   // (D,D)
    const float* W1     = (const float*)d_in[3];   // (D,D)
    const float* bn0_g  = (const float*)d_in[4];
    const float* bn0_b  = (const float*)d_in[5];
    const float* bn1_g  = (const float*)d_in[6];
    const float* bn1_b  = (const float*)d_in[7];
    const int*   cmask  = (const int*)d_in[8];     // (B,C)
    const int*   kmask  = (const int*)d_in[9];     // (B,K)
    const int*   klen   = (const int*)d_in[10];    // (B,)

    float* out  = (float*)d_out;
    float* out1 = out;                                   // (B,C,D)
    float* out2 = out + (long)BCD;                       // (B,C,K,D)
    float* out3 = out + (long)BCD + (long)PB*PC*PK*PD;   // (B,C,K)

    float *raw0, *raw1;
    cudaGetSymbolAddress((void**)&raw0, g_raw0);
    cudaGetSymbolAddress((void**)&raw1, g_raw1);

    // 1) dual GEMM (uncapped prefetch) + zerofill ALL mask-zero rows (~200MB)
    kernel1<<<256 + ZB1, 256>>>(q, kc, W0, W1, raw0, raw1, cmask, kmask, out2);

    // 2) BN stats+apply+sigmoid+t1 (solo)
    bn_merged<<<256, 256>>>(bn0_g, bn0_b, bn1_g, bn1_b, kc);

    // 3) out3 GEMM + persistent balanced nonzero stream + out1
    kernel3<<<64 + SB3, 256>>>(cmask, kmask, klen, out1, out2, out3);
}